// round 1
// baseline (speedup 1.0000x reference)
#include <cuda_runtime.h>
#include <math.h>

#define BB 16
#define NN 128
#define MM 64
#define DD 512
#define HH 4
#define KK 128
#define LL 3
#define AT_NB 4

// ---------------- scratch (device globals; no allocation allowed) ----------
__device__ float d_w[BB * NN * DD];      // word projection  [B,N,D]
__device__ float d_r[BB * MM * DD];      // rel projection   [B,M,D]
__device__ float d_v[HH * DD];           // lin_w . score_w  [H,D]
__device__ float d_c[HH];                // lin_b . score_w + score_b
__device__ float d_G[BB * HH * DD];      // mean_n sum_m wts*had  [B,H,D]
__device__ float d_Wsum[BB * HH];        // mean_n sum_m wts      [B,H]

// ---------------- kernel 1: precompute v, c; zero accumulators -------------
__global__ void init_kernel(const float* __restrict__ lin_w,
                            const float* __restrict__ lin_b,
                            const float* __restrict__ score_w,
                            const float* __restrict__ score_b) {
    int gid = blockIdx.x * blockDim.x + threadIdx.x;   // grid 16*256 = 4096
    if (gid < HH * DD) {
        int h = gid >> 9, d = gid & (DD - 1);
        const float* lp = lin_w + (h * DD + d) * KK;
        const float* sp = score_w + h * KK;
        float acc = 0.f;
#pragma unroll 8
        for (int k = 0; k < KK; k++) acc = fmaf(lp[k], sp[k], acc);
        d_v[gid] = acc;
    } else if (gid < HH * DD + HH) {
        int h = gid - HH * DD;
        float acc = score_b[h];
        for (int k = 0; k < KK; k++)
            acc = fmaf(lin_b[h * KK + k], score_w[h * KK + k], acc);
        d_c[h] = acc;
    }
    for (int i = gid; i < BB * HH * DD; i += 4096) d_G[i] = 0.f;
    if (gid < BB * HH) d_Wsum[gid] = 0.f;
}

// ---------------- kernel 2: fused projections (both GEMMs) -----------------
// C = A @ W + bias.  z=0: word[2048,512]@Wn -> d_w ; z=1: rel[1024,512]@Wr -> d_r
__global__ __launch_bounds__(256) void gemm_kernel(
    const float* __restrict__ word, const float* __restrict__ Wn_w,
    const float* __restrict__ Wn_b, const float* __restrict__ rel,
    const float* __restrict__ Wr_w, const float* __restrict__ Wr_b) {
    const int z = blockIdx.z;
    const int Mrows = (z == 0) ? (BB * NN) : (BB * MM);
    if ((int)blockIdx.y * 64 >= Mrows) return;
    const float* A    = (z == 0) ? word : rel;
    const float* W    = (z == 0) ? Wn_w : Wr_w;
    const float* bias = (z == 0) ? Wn_b : Wr_b;
    float* C          = (z == 0) ? d_w : d_r;

    __shared__ float As[16][64];   // As[k][m]
    __shared__ float Bs[16][64];   // Bs[k][n]

    const int tid = threadIdx.x;
    const int m0 = blockIdx.y * 64;
    const int n0 = blockIdx.x * 64;
    const int ty = tid >> 4, tx = tid & 15;

    const int ar = tid >> 2;            // 0..63 (row in A tile)
    const int aq = (tid & 3) * 4;       // k quad
    const int br = tid >> 4;            // 0..15 (k row in B tile)
    const int bq = (tid & 15) * 4;      // n quad

    float acc[4][4] = {};
    for (int k0 = 0; k0 < DD; k0 += 16) {
        float4 av = *(const float4*)(A + (size_t)(m0 + ar) * DD + k0 + aq);
        float4 bv = *(const float4*)(W + (size_t)(k0 + br) * DD + n0 + bq);
        __syncthreads();
        As[aq + 0][ar] = av.x; As[aq + 1][ar] = av.y;
        As[aq + 2][ar] = av.z; As[aq + 3][ar] = av.w;
        *(float4*)&Bs[br][bq] = bv;
        __syncthreads();
#pragma unroll
        for (int k = 0; k < 16; k++) {
            float4 a = *(const float4*)&As[k][ty * 4];
            float4 b = *(const float4*)&Bs[k][tx * 4];
            acc[0][0] = fmaf(a.x, b.x, acc[0][0]);
            acc[0][1] = fmaf(a.x, b.y, acc[0][1]);
            acc[0][2] = fmaf(a.x, b.z, acc[0][2]);
            acc[0][3] = fmaf(a.x, b.w, acc[0][3]);
            acc[1][0] = fmaf(a.y, b.x, acc[1][0]);
            acc[1][1] = fmaf(a.y, b.y, acc[1][1]);
            acc[1][2] = fmaf(a.y, b.z, acc[1][2]);
            acc[1][3] = fmaf(a.y, b.w, acc[1][3]);
            acc[2][0] = fmaf(a.z, b.x, acc[2][0]);
            acc[2][1] = fmaf(a.z, b.y, acc[2][1]);
            acc[2][2] = fmaf(a.z, b.z, acc[2][2]);
            acc[2][3] = fmaf(a.z, b.w, acc[2][3]);
            acc[3][0] = fmaf(a.w, b.x, acc[3][0]);
            acc[3][1] = fmaf(a.w, b.y, acc[3][1]);
            acc[3][2] = fmaf(a.w, b.z, acc[3][2]);
            acc[3][3] = fmaf(a.w, b.w, acc[3][3]);
        }
    }
    float4 bb = *(const float4*)(bias + n0 + tx * 4);
#pragma unroll
    for (int i = 0; i < 4; i++) {
        float4 o;
        o.x = acc[i][0] + bb.x; o.y = acc[i][1] + bb.y;
        o.z = acc[i][2] + bb.z; o.w = acc[i][3] + bb.w;
        *(float4*)(C + (size_t)(m0 + ty * 4 + i) * DD + n0 + tx * 4) = o;
    }
}

// ---------------- kernel 3: fused attention core ----------------------------
// One CTA per (b, tile of AT_NB n's). r[b] staged in SMEM, v in registers.
__global__ __launch_bounds__(256, 1) void attn_kernel(const float* __restrict__ mask) {
    extern __shared__ float sm[];
    float* r_s    = sm;                          // MM*DD = 32768
    float* w_s    = r_s + MM * DD;               // AT_NB*DD = 2048
    float* sw_s   = w_s + AT_NB * DD;            // AT_NB*MM*HH = 1024 (scores->wts)
    float* mask_s = sw_s + AT_NB * MM * HH;      // 64
    __shared__ float c_s[HH];

    const int b   = blockIdx.y;
    const int n0  = blockIdx.x * AT_NB;
    const int tid = threadIdx.x;
    const int wid = tid >> 5, lane = tid & 31;

    // stage r[b] (128 KB) and the AT_NB w rows
    const float4* rg = (const float4*)(d_r + (size_t)b * MM * DD);
    float4* rs4 = (float4*)r_s;
#pragma unroll 4
    for (int i = tid; i < MM * DD / 4; i += 256) rs4[i] = rg[i];
    const float4* wg = (const float4*)(d_w + (size_t)(b * NN + n0) * DD);
    float4* ws4 = (float4*)w_s;
#pragma unroll
    for (int i = tid; i < AT_NB * DD / 4; i += 256) ws4[i] = wg[i];
    if (tid < MM) mask_s[tid] = mask[b * MM + tid];
    if (tid < HH) c_s[tid] = d_c[tid];

    // v cached in registers: per-lane slice d = lane + 32*i
    float vr[HH][16];
#pragma unroll
    for (int h = 0; h < HH; h++)
#pragma unroll
        for (int i = 0; i < 16; i++)
            vr[h][i] = d_v[h * DD + lane + 32 * i];

    __syncthreads();

    // ---- pass 1: scores s[nn][m][h] ----
#pragma unroll 1
    for (int nn = 0; nn < AT_NB; nn++) {
        float wreg[16];
#pragma unroll
        for (int i = 0; i < 16; i++) wreg[i] = w_s[nn * DD + lane + 32 * i];
#pragma unroll 1
        for (int mi = 0; mi < 8; mi++) {
            int m = wid * 8 + mi;
            const float* rrow = r_s + m * DD;
            float a0 = 0.f, a1 = 0.f, a2 = 0.f, a3 = 0.f;
#pragma unroll
            for (int i = 0; i < 16; i++) {
                float hv = fmaxf(wreg[i] * rrow[lane + 32 * i], 0.f);
                a0 = fmaf(hv, vr[0][i], a0);
                a1 = fmaf(hv, vr[1][i], a1);
                a2 = fmaf(hv, vr[2][i], a2);
                a3 = fmaf(hv, vr[3][i], a3);
            }
#pragma unroll
            for (int off = 16; off; off >>= 1) {
                a0 += __shfl_xor_sync(0xffffffffu, a0, off);
                a1 += __shfl_xor_sync(0xffffffffu, a1, off);
                a2 += __shfl_xor_sync(0xffffffffu, a2, off);
                a3 += __shfl_xor_sync(0xffffffffu, a3, off);
            }
            if (lane == 0) {
                float* sp = sw_s + (nn * MM + m) * HH;
                sp[0] = a0 + c_s[0]; sp[1] = a1 + c_s[1];
                sp[2] = a2 + c_s[2]; sp[3] = a3 + c_s[3];
            }
        }
    }
    __syncthreads();

    // ---- softmax over m (per nn,h), overwrite sw_s with wts, acc Wsum ----
    for (int p = wid; p < AT_NB * HH; p += 8) {
        int nn = p >> 2, h = p & 3;
        float x0 = sw_s[(nn * MM + lane) * HH + h];
        float x1 = sw_s[(nn * MM + lane + 32) * HH + h];
        float mx = fmaxf(x0, x1);
#pragma unroll
        for (int off = 16; off; off >>= 1)
            mx = fmaxf(mx, __shfl_xor_sync(0xffffffffu, mx, off));
        float e0 = __expf(x0 - mx), e1 = __expf(x1 - mx);
        float s = e0 + e1;
#pragma unroll
        for (int off = 16; off; off >>= 1)
            s += __shfl_xor_sync(0xffffffffu, s, off);
        float inv = 1.f / s;
        float w0 = e0 * inv * mask_s[lane];
        float w1 = e1 * inv * mask_s[lane + 32];
        sw_s[(nn * MM + lane) * HH + h] = w0;
        sw_s[(nn * MM + lane + 32) * HH + h] = w1;
        float ws = w0 + w1;
#pragma unroll
        for (int off = 16; off; off >>= 1)
            ws += __shfl_xor_sync(0xffffffffu, ws, off);
        if (lane == 0) atomicAdd(&d_Wsum[b * HH + h], ws * (1.f / (float)NN));
    }
    __syncthreads();

    // ---- pass 2: g[h][d] = sum_nn sum_m wts * relu(w*r) ----
    const int dA = tid, dB = tid + 256;
    float g[HH][2] = {};
#pragma unroll 1
    for (int nn = 0; nn < AT_NB; nn++) {
        float wn0 = w_s[nn * DD + dA], wn1 = w_s[nn * DD + dB];
        const float* swp = sw_s + nn * MM * HH;
#pragma unroll 4
        for (int m = 0; m < MM; m++) {
            float hv0 = fmaxf(wn0 * r_s[m * DD + dA], 0.f);
            float hv1 = fmaxf(wn1 * r_s[m * DD + dB], 0.f);
            float4 t = *(const float4*)(swp + m * HH);
            g[0][0] = fmaf(t.x, hv0, g[0][0]); g[0][1] = fmaf(t.x, hv1, g[0][1]);
            g[1][0] = fmaf(t.y, hv0, g[1][0]); g[1][1] = fmaf(t.y, hv1, g[1][1]);
            g[2][0] = fmaf(t.z, hv0, g[2][0]); g[2][1] = fmaf(t.z, hv1, g[2][1]);
            g[3][0] = fmaf(t.w, hv0, g[3][0]); g[3][1] = fmaf(t.w, hv1, g[3][1]);
        }
    }
#pragma unroll
    for (int h = 0; h < HH; h++) {
        atomicAdd(&d_G[(b * HH + h) * DD + dA], g[h][0] * (1.f / (float)NN));
        atomicAdd(&d_G[(b * HH + h) * DD + dB], g[h][1] * (1.f / (float)NN));
    }
}

// ---------------- kernel 4: head projection + final + fc -------------------
__global__ __launch_bounds__(256) void finish_kernel(
    const float* __restrict__ lin_w, const float* __restrict__ lin_b,
    const float* __restrict__ final_w, const float* __restrict__ final_b,
    const float* __restrict__ fc_w, const float* __restrict__ fc_b,
    float* __restrict__ out) {
    const int b = blockIdx.x;
    const int tid = threadIdx.x;
    __shared__ float head_s[DD];
    __shared__ float out_s[DD];

    for (int idx = tid; idx < DD; idx += 256) {
        int h = idx >> 7, k = idx & (KK - 1);
        float acc = d_Wsum[b * HH + h] * lin_b[h * KK + k];
        const float* Gp = d_G + (size_t)(b * HH + h) * DD;
        const float* Lp = lin_w + (size_t)h * DD * KK + k;
#pragma unroll 8
        for (int d = 0; d < DD; d++) acc = fmaf(Gp[d], Lp[(size_t)d * KK], acc);
        head_s[idx] = acc;
    }
    __syncthreads();
    for (int idx = tid; idx < DD; idx += 256) {
        float acc = final_b[idx];
#pragma unroll 8
        for (int i = 0; i < DD; i++)
            acc = fmaf(head_s[i], final_w[(size_t)i * DD + idx], acc);
        out_s[idx] = fmaxf(acc, 0.f);
    }
    __syncthreads();
    if (tid < LL) {
        float acc = fc_b[tid];
#pragma unroll 8
        for (int j = 0; j < DD; j++)
            acc = fmaf(out_s[j], fc_w[j * LL + tid], acc);
        out[b * LL + tid] = acc;
    }
}

// ---------------- launcher ---------------------------------------------------
extern "C" void kernel_launch(void* const* d_in, const int* in_sizes, int n_in,
                              void* d_out, int out_size) {
    const float* word    = (const float*)d_in[0];
    const float* rel     = (const float*)d_in[1];
    const float* mask    = (const float*)d_in[2];
    const float* Wn_w    = (const float*)d_in[3];
    const float* Wn_b    = (const float*)d_in[4];
    const float* Wr_w    = (const float*)d_in[5];
    const float* Wr_b    = (const float*)d_in[6];
    const float* lin_w   = (const float*)d_in[7];
    const float* lin_b   = (const float*)d_in[8];
    const float* score_w = (const float*)d_in[9];
    const float* score_b = (const float*)d_in[10];
    const float* final_w = (const float*)d_in[11];
    const float* final_b = (const float*)d_in[12];
    const float* fc_w    = (const float*)d_in[13];
    const float* fc_b    = (const float*)d_in[14];
    float* out = (float*)d_out;

    init_kernel<<<16, 256>>>(lin_w, lin_b, score_w, score_b);

    gemm_kernel<<<dim3(DD / 64, (BB * NN) / 64, 2), 256>>>(
        word, Wn_w, Wn_b, rel, Wr_w, Wr_b);

    const int smem_bytes = (MM * DD + AT_NB * DD + AT_NB * MM * HH + 64) * 4;
    cudaFuncSetAttribute(attn_kernel,
                         cudaFuncAttributeMaxDynamicSharedMemorySize, smem_bytes);
    attn_kernel<<<dim3(NN / AT_NB, BB), 256, smem_bytes>>>(mask);

    finish_kernel<<<BB, 256>>>(lin_w, lin_b, final_w, final_b, fc_w, fc_b, out);
}

// round 2
// speedup vs baseline: 1.2430x; 1.2430x over previous
#include <cuda_runtime.h>
#include <math.h>

#define BB 16
#define NN 128
#define MM 64
#define DD 512
#define HH 4
#define KK 128
#define LL 3
#define AT_NB 8

// ---------------- scratch (device globals; no allocation allowed) ----------
__device__ float d_w[BB * NN * DD];      // word projection  [B,N,D]
__device__ float d_r[BB * MM * DD];      // rel projection   [B,M,D]
__device__ float d_v[HH * DD];           // lin_w . score_w  [H,D]
__device__ float d_c[HH];                // lin_b . score_w + score_b
__device__ float d_G[BB * HH * DD];      // mean_n sum_m wts*had  [B,H,D]
__device__ float d_Wsum[BB * HH];        // mean_n sum_m wts      [B,H]
__device__ float d_head[BB * DD];        // concat heads          [B,D]
__device__ float d_o2[BB * DD];          // relu(final proj)      [B,D]

// ---------------- kernel 1: precompute v, c; zero accumulators -------------
__global__ void init_kernel(const float* __restrict__ lin_w,
                            const float* __restrict__ lin_b,
                            const float* __restrict__ score_w,
                            const float* __restrict__ score_b) {
    int gid = blockIdx.x * blockDim.x + threadIdx.x;   // grid 16*256 = 4096
    if (gid < HH * DD) {
        int h = gid >> 9, d = gid & (DD - 1);
        const float* lp = lin_w + (h * DD + d) * KK;
        const float* sp = score_w + h * KK;
        float acc = 0.f;
#pragma unroll 8
        for (int k = 0; k < KK; k++) acc = fmaf(lp[k], sp[k], acc);
        d_v[gid] = acc;
    } else if (gid < HH * DD + HH) {
        int h = gid - HH * DD;
        float acc = score_b[h];
        for (int k = 0; k < KK; k++)
            acc = fmaf(lin_b[h * KK + k], score_w[h * KK + k], acc);
        d_c[h] = acc;
    }
    for (int i = gid; i < BB * HH * DD; i += 4096) d_G[i] = 0.f;
    if (gid < BB * HH) d_Wsum[gid] = 0.f;
}

// ---------------- kernel 2: fused projections (both GEMMs) -----------------
// C = A @ W + bias.  z=0: word[2048,512]@Wn -> d_w ; z=1: rel[1024,512]@Wr -> d_r
__global__ __launch_bounds__(256) void gemm_kernel(
    const float* __restrict__ word, const float* __restrict__ Wn_w,
    const float* __restrict__ Wn_b, const float* __restrict__ rel,
    const float* __restrict__ Wr_w, const float* __restrict__ Wr_b) {
    const int z = blockIdx.z;
    const int Mrows = (z == 0) ? (BB * NN) : (BB * MM);
    if ((int)blockIdx.y * 64 >= Mrows) return;
    const float* A    = (z == 0) ? word : rel;
    const float* W    = (z == 0) ? Wn_w : Wr_w;
    const float* bias = (z == 0) ? Wn_b : Wr_b;
    float* C          = (z == 0) ? d_w : d_r;

    __shared__ float As[16][64];   // As[k][m]
    __shared__ float Bs[16][64];   // Bs[k][n]

    const int tid = threadIdx.x;
    const int m0 = blockIdx.y * 64;
    const int n0 = blockIdx.x * 64;
    const int ty = tid >> 4, tx = tid & 15;

    const int ar = tid >> 2;            // 0..63 (row in A tile)
    const int aq = (tid & 3) * 4;       // k quad
    const int br = tid >> 4;            // 0..15 (k row in B tile)
    const int bq = (tid & 15) * 4;      // n quad

    float acc[4][4] = {};
    for (int k0 = 0; k0 < DD; k0 += 16) {
        float4 av = *(const float4*)(A + (size_t)(m0 + ar) * DD + k0 + aq);
        float4 bv = *(const float4*)(W + (size_t)(k0 + br) * DD + n0 + bq);
        __syncthreads();
        As[aq + 0][ar] = av.x; As[aq + 1][ar] = av.y;
        As[aq + 2][ar] = av.z; As[aq + 3][ar] = av.w;
        *(float4*)&Bs[br][bq] = bv;
        __syncthreads();
#pragma unroll
        for (int k = 0; k < 16; k++) {
            float4 a = *(const float4*)&As[k][ty * 4];
            float4 b = *(const float4*)&Bs[k][tx * 4];
            acc[0][0] = fmaf(a.x, b.x, acc[0][0]);
            acc[0][1] = fmaf(a.x, b.y, acc[0][1]);
            acc[0][2] = fmaf(a.x, b.z, acc[0][2]);
            acc[0][3] = fmaf(a.x, b.w, acc[0][3]);
            acc[1][0] = fmaf(a.y, b.x, acc[1][0]);
            acc[1][1] = fmaf(a.y, b.y, acc[1][1]);
            acc[1][2] = fmaf(a.y, b.z, acc[1][2]);
            acc[1][3] = fmaf(a.y, b.w, acc[1][3]);
            acc[2][0] = fmaf(a.z, b.x, acc[2][0]);
            acc[2][1] = fmaf(a.z, b.y, acc[2][1]);
            acc[2][2] = fmaf(a.z, b.z, acc[2][2]);
            acc[2][3] = fmaf(a.z, b.w, acc[2][3]);
            acc[3][0] = fmaf(a.w, b.x, acc[3][0]);
            acc[3][1] = fmaf(a.w, b.y, acc[3][1]);
            acc[3][2] = fmaf(a.w, b.z, acc[3][2]);
            acc[3][3] = fmaf(a.w, b.w, acc[3][3]);
        }
    }
    float4 bb = *(const float4*)(bias + n0 + tx * 4);
#pragma unroll
    for (int i = 0; i < 4; i++) {
        float4 o;
        o.x = acc[i][0] + bb.x; o.y = acc[i][1] + bb.y;
        o.z = acc[i][2] + bb.z; o.w = acc[i][3] + bb.w;
        *(float4*)(C + (size_t)(m0 + ty * 4 + i) * DD + n0 + tx * 4) = o;
    }
}

// ---------------- kernel 3: fused attention core ----------------------------
// One CTA per (b, tile of AT_NB n's). r[b] staged in SMEM, v in registers.
__global__ __launch_bounds__(256, 1) void attn_kernel(const float* __restrict__ mask) {
    extern __shared__ float sm[];
    float* r_s    = sm;                          // MM*DD = 32768
    float* w_s    = r_s + MM * DD;               // AT_NB*DD
    float* sw_s   = w_s + AT_NB * DD;            // AT_NB*MM*HH (scores->wts)
    float* mask_s = sw_s + AT_NB * MM * HH;      // 64
    __shared__ float c_s[HH];

    const int b   = blockIdx.y;
    const int n0  = blockIdx.x * AT_NB;
    const int tid = threadIdx.x;
    const int wid = tid >> 5, lane = tid & 31;

    // stage r[b] (128 KB) and the AT_NB w rows
    const float4* rg = (const float4*)(d_r + (size_t)b * MM * DD);
    float4* rs4 = (float4*)r_s;
#pragma unroll 4
    for (int i = tid; i < MM * DD / 4; i += 256) rs4[i] = rg[i];
    const float4* wg = (const float4*)(d_w + (size_t)(b * NN + n0) * DD);
    float4* ws4 = (float4*)w_s;
#pragma unroll
    for (int i = tid; i < AT_NB * DD / 4; i += 256) ws4[i] = wg[i];
    if (tid < MM) mask_s[tid] = mask[b * MM + tid];
    if (tid < HH) c_s[tid] = d_c[tid];

    // v cached in registers: per-lane slice d = lane + 32*i
    float vr[HH][16];
#pragma unroll
    for (int h = 0; h < HH; h++)
#pragma unroll
        for (int i = 0; i < 16; i++)
            vr[h][i] = d_v[h * DD + lane + 32 * i];

    __syncthreads();

    // ---- pass 1: scores s[nn][m][h] ----
#pragma unroll 1
    for (int nn = 0; nn < AT_NB; nn++) {
        float wreg[16];
#pragma unroll
        for (int i = 0; i < 16; i++) wreg[i] = w_s[nn * DD + lane + 32 * i];
#pragma unroll 1
        for (int mi = 0; mi < 8; mi++) {
            int m = wid * 8 + mi;
            const float* rrow = r_s + m * DD;
            float a0 = 0.f, a1 = 0.f, a2 = 0.f, a3 = 0.f;
#pragma unroll
            for (int i = 0; i < 16; i++) {
                float hv = fmaxf(wreg[i] * rrow[lane + 32 * i], 0.f);
                a0 = fmaf(hv, vr[0][i], a0);
                a1 = fmaf(hv, vr[1][i], a1);
                a2 = fmaf(hv, vr[2][i], a2);
                a3 = fmaf(hv, vr[3][i], a3);
            }
#pragma unroll
            for (int off = 16; off; off >>= 1) {
                a0 += __shfl_xor_sync(0xffffffffu, a0, off);
                a1 += __shfl_xor_sync(0xffffffffu, a1, off);
                a2 += __shfl_xor_sync(0xffffffffu, a2, off);
                a3 += __shfl_xor_sync(0xffffffffu, a3, off);
            }
            if (lane == 0) {
                float* sp = sw_s + (nn * MM + m) * HH;
                sp[0] = a0 + c_s[0]; sp[1] = a1 + c_s[1];
                sp[2] = a2 + c_s[2]; sp[3] = a3 + c_s[3];
            }
        }
    }
    __syncthreads();

    // ---- softmax over m (per nn,h), overwrite sw_s with wts, acc Wsum ----
    for (int p = wid; p < AT_NB * HH; p += 8) {
        int nn = p >> 2, h = p & 3;
        float x0 = sw_s[(nn * MM + lane) * HH + h];
        float x1 = sw_s[(nn * MM + lane + 32) * HH + h];
        float mx = fmaxf(x0, x1);
#pragma unroll
        for (int off = 16; off; off >>= 1)
            mx = fmaxf(mx, __shfl_xor_sync(0xffffffffu, mx, off));
        float e0 = __expf(x0 - mx), e1 = __expf(x1 - mx);
        float s = e0 + e1;
#pragma unroll
        for (int off = 16; off; off >>= 1)
            s += __shfl_xor_sync(0xffffffffu, s, off);
        float inv = 1.f / s;
        float w0 = e0 * inv * mask_s[lane];
        float w1 = e1 * inv * mask_s[lane + 32];
        sw_s[(nn * MM + lane) * HH + h] = w0;
        sw_s[(nn * MM + lane + 32) * HH + h] = w1;
        float ws = w0 + w1;
#pragma unroll
        for (int off = 16; off; off >>= 1)
            ws += __shfl_xor_sync(0xffffffffu, ws, off);
        if (lane == 0) atomicAdd(&d_Wsum[b * HH + h], ws * (1.f / (float)NN));
    }
    __syncthreads();

    // ---- pass 2: g[h][d] = sum_nn sum_m wts * relu(w*r) ----
    const int dA = tid, dB = tid + 256;
    float g[HH][2] = {};
#pragma unroll 1
    for (int nn = 0; nn < AT_NB; nn++) {
        float wn0 = w_s[nn * DD + dA], wn1 = w_s[nn * DD + dB];
        const float* swp = sw_s + nn * MM * HH;
#pragma unroll 4
        for (int m = 0; m < MM; m++) {
            float hv0 = fmaxf(wn0 * r_s[m * DD + dA], 0.f);
            float hv1 = fmaxf(wn1 * r_s[m * DD + dB], 0.f);
            float4 t = *(const float4*)(swp + m * HH);
            g[0][0] = fmaf(t.x, hv0, g[0][0]); g[0][1] = fmaf(t.x, hv1, g[0][1]);
            g[1][0] = fmaf(t.y, hv0, g[1][0]); g[1][1] = fmaf(t.y, hv1, g[1][1]);
            g[2][0] = fmaf(t.z, hv0, g[2][0]); g[2][1] = fmaf(t.z, hv1, g[2][1]);
            g[3][0] = fmaf(t.w, hv0, g[3][0]); g[3][1] = fmaf(t.w, hv1, g[3][1]);
        }
    }
#pragma unroll
    for (int h = 0; h < HH; h++) {
        atomicAdd(&d_G[(b * HH + h) * DD + dA], g[h][0] * (1.f / (float)NN));
        atomicAdd(&d_G[(b * HH + h) * DD + dB], g[h][1] * (1.f / (float)NN));
    }
}

// ---------------- kernel 4: head projection  head[b,h*K+k] -----------------
// grid (BB, HH), block 256. Coalesced over k (lin_w contiguous in k).
__global__ __launch_bounds__(256) void head_kernel(
    const float* __restrict__ lin_w, const float* __restrict__ lin_b) {
    const int b = blockIdx.x, h = blockIdx.y;
    const int tid = threadIdx.x;
    __shared__ float Gs[DD];
    __shared__ float part[256];
    for (int i = tid; i < DD; i += 256)
        Gs[i] = d_G[(size_t)(b * HH + h) * DD + i];
    __syncthreads();
    const int k = tid & 127, half = tid >> 7;   // d split in two halves
    float acc = (half == 0) ? d_Wsum[b * HH + h] * lin_b[h * KK + k] : 0.f;
    const float* Lp = lin_w + ((size_t)h * DD + half * 256) * KK + k;
    const float* Gp = Gs + half * 256;
#pragma unroll 8
    for (int d = 0; d < 256; d++)
        acc = fmaf(Gp[d], Lp[(size_t)d * KK], acc);
    part[tid] = acc;
    __syncthreads();
    if (half == 0)
        d_head[b * DD + h * KK + k] = part[k] + part[k + 128];
}

// ---------------- kernel 5: final projection + relu -------------------------
// grid (BB, 4) j-tiles of 128, block 256. Coalesced over j.
__global__ __launch_bounds__(256) void final_kernel(
    const float* __restrict__ final_w, const float* __restrict__ final_b) {
    const int b = blockIdx.x, j0 = blockIdx.y * 128;
    const int tid = threadIdx.x;
    __shared__ float hs[DD];
    __shared__ float part[256];
    for (int i = tid; i < DD; i += 256) hs[i] = d_head[b * DD + i];
    __syncthreads();
    const int j = tid & 127, half = tid >> 7;
    float acc = 0.f;
    const float* Fp = final_w + (size_t)(half * 256) * DD + j0 + j;
    const float* Hp = hs + half * 256;
#pragma unroll 8
    for (int i = 0; i < 256; i++)
        acc = fmaf(Hp[i], Fp[(size_t)i * DD], acc);
    part[tid] = acc;
    __syncthreads();
    if (half == 0)
        d_o2[b * DD + j0 + j] =
            fmaxf(part[j] + part[j + 128] + final_b[j0 + j], 0.f);
}

// ---------------- kernel 6: fc logits ---------------------------------------
__global__ __launch_bounds__(128) void fc_kernel(
    const float* __restrict__ fc_w, const float* __restrict__ fc_b,
    float* __restrict__ out) {
    const int b = blockIdx.x;
    const int tid = threadIdx.x;
    const int wid = tid >> 5, lane = tid & 31;
    __shared__ float os[DD];
    for (int i = tid; i < DD; i += 128) os[i] = d_o2[b * DD + i];
    __syncthreads();
    if (wid < LL) {
        float acc = 0.f;
#pragma unroll 4
        for (int i = lane; i < DD; i += 32)
            acc = fmaf(os[i], fc_w[i * LL + wid], acc);
#pragma unroll
        for (int off = 16; off; off >>= 1)
            acc += __shfl_xor_sync(0xffffffffu, acc, off);
        if (lane == 0) out[b * LL + wid] = acc + fc_b[wid];
    }
}

// ---------------- launcher ---------------------------------------------------
extern "C" void kernel_launch(void* const* d_in, const int* in_sizes, int n_in,
                              void* d_out, int out_size) {
    const float* word    = (const float*)d_in[0];
    const float* rel     = (const float*)d_in[1];
    const float* mask    = (const float*)d_in[2];
    const float* Wn_w    = (const float*)d_in[3];
    const float* Wn_b    = (const float*)d_in[4];
    const float* Wr_w    = (const float*)d_in[5];
    const float* Wr_b    = (const float*)d_in[6];
    const float* lin_w   = (const float*)d_in[7];
    const float* lin_b   = (const float*)d_in[8];
    const float* score_w = (const float*)d_in[9];
    const float* score_b = (const float*)d_in[10];
    const float* final_w = (const float*)d_in[11];
    const float* final_b = (const float*)d_in[12];
    const float* fc_w    = (const float*)d_in[13];
    const float* fc_b    = (const float*)d_in[14];
    float* out = (float*)d_out;

    init_kernel<<<16, 256>>>(lin_w, lin_b, score_w, score_b);

    gemm_kernel<<<dim3(DD / 64, (BB * NN) / 64, 2), 256>>>(
        word, Wn_w, Wn_b, rel, Wr_w, Wr_b);

    const int smem_bytes = (MM * DD + AT_NB * DD + AT_NB * MM * HH + 64) * 4;
    cudaFuncSetAttribute(attn_kernel,
                         cudaFuncAttributeMaxDynamicSharedMemorySize, smem_bytes);
    attn_kernel<<<dim3(NN / AT_NB, BB), 256, smem_bytes>>>(mask);

    head_kernel<<<dim3(BB, HH), 256>>>(lin_w, lin_b);
    final_kernel<<<dim3(BB, 4), 256>>>(final_w, final_b);
    fc_kernel<<<BB, 128>>>(fc_w, fc_b, out);
}

// round 3
// speedup vs baseline: 1.2450x; 1.0017x over previous
#include <cuda_runtime.h>
#include <math.h>

#define BB 16
#define NN 128
#define MM 64
#define DD 512
#define HH 4
#define KK 128
#define LL 3
#define AT_NB 8

// ---------------- scratch (device globals; no allocation allowed) ----------
__device__ float d_w[BB * NN * DD];      // word projection  [B,N,D]
__device__ float d_r[BB * MM * DD];      // rel projection   [B,M,D]
__device__ float d_v[HH * DD];           // lin_w . score_w  [H,D]
__device__ float d_c[HH];                // lin_b . score_w + score_b
__device__ float d_G[BB * HH * DD];      // mean_n sum_m wts*had  [B,H,D]
__device__ float d_Wsum[BB * HH];        // mean_n sum_m wts      [B,H]
__device__ float d_head[BB * DD];        // concat heads          [B,D]
__device__ float d_o2[BB * DD];          // final proj pre-relu   [B,D]

// packed dual-fp32 fma (sm_100+; ptxas never emits from C++)
__device__ __forceinline__ void fma2(unsigned long long& d,
                                     unsigned long long a,
                                     unsigned long long b) {
    asm("fma.rn.f32x2 %0, %1, %2, %3;" : "=l"(d) : "l"(a), "l"(b), "l"(d));
}

// ---------------- kernel 1: precompute v, c; init accumulators -------------
__global__ void init_kernel(const float* __restrict__ lin_w,
                            const float* __restrict__ lin_b,
                            const float* __restrict__ score_w,
                            const float* __restrict__ score_b,
                            const float* __restrict__ final_b) {
    int gid = blockIdx.x * blockDim.x + threadIdx.x;   // 4096 threads
    if (gid < HH * DD) {
        int h = gid >> 9, d = gid & (DD - 1);
        const float* lp = lin_w + (h * DD + d) * KK;
        const float* sp = score_w + h * KK;
        float acc = 0.f;
#pragma unroll 8
        for (int k = 0; k < KK; k++) acc = fmaf(lp[k], sp[k], acc);
        d_v[gid] = acc;
    } else if (gid < HH * DD + HH) {
        int h = gid - HH * DD;
        float acc = score_b[h];
        for (int k = 0; k < KK; k++)
            acc = fmaf(lin_b[h * KK + k], score_w[h * KK + k], acc);
        d_c[h] = acc;
    }
    for (int i = gid; i < BB * HH * DD; i += 4096) d_G[i] = 0.f;
    for (int i = gid; i < BB * DD; i += 4096) {
        d_head[i] = 0.f;
        d_o2[i] = final_b[i & (DD - 1)];
    }
    if (gid < BB * HH) d_Wsum[gid] = 0.f;
}

// ---------------- kernel 2: fused projections, f32x2 dual-FMA --------------
// 128x128 tiles, 8x8 thread tile, k-pair packing in SMEM (k-minor layout).
#define AS_K 18   // padded k-stride (words) for conflict-free LDS.64
__global__ __launch_bounds__(256, 1) void gemm_kernel(
    const float* __restrict__ word, const float* __restrict__ Wn_w,
    const float* __restrict__ Wn_b, const float* __restrict__ rel,
    const float* __restrict__ Wr_w, const float* __restrict__ Wr_b) {
    const int z = blockIdx.z;
    const int mtiles = (z == 0) ? (BB * NN / 128) : (BB * MM / 128);
    if ((int)blockIdx.y >= mtiles) return;
    const float* A    = (z == 0) ? word : rel;
    const float* W    = (z == 0) ? Wn_w : Wr_w;
    const float* bias = (z == 0) ? Wn_b : Wr_b;
    float* C          = (z == 0) ? d_w : d_r;

    __shared__ __align__(16) float As[128 * AS_K];  // [m][k] k-minor
    __shared__ __align__(16) float Bs[128 * AS_K];  // [n][k] k-minor

    const int tid = threadIdx.x;
    const int m0 = blockIdx.y * 128;
    const int n0 = blockIdx.x * 128;
    const int ty = tid >> 4, tx = tid & 15;

    unsigned long long acc2[8][8];
#pragma unroll
    for (int i = 0; i < 8; i++)
#pragma unroll
        for (int j = 0; j < 8; j++) acc2[i][j] = 0ull;

    for (int k0 = 0; k0 < DD; k0 += 16) {
        __syncthreads();
        // stage A tile: [128 m][16 k], k-minor (no transpose, global k-contig)
#pragma unroll
        for (int s = 0; s < 2; s++) {
            int idx = tid + s * 256;              // 0..511
            int m = idx >> 2, kq = (idx & 3) * 4;
            float4 v = *(const float4*)(A + (size_t)(m0 + m) * DD + k0 + kq);
            float2* pa = (float2*)&As[m * AS_K + kq];
            pa[0] = make_float2(v.x, v.y);
            pa[1] = make_float2(v.z, v.w);
        }
        // stage B tile transposed: global [k][n] -> Bs [n][k]
#pragma unroll
        for (int s = 0; s < 2; s++) {
            int idx = tid + s * 256;              // 0..511
            int k = idx >> 5, nq = (idx & 31) * 4;
            float4 v = *(const float4*)(W + (size_t)(k0 + k) * DD + n0 + nq);
            Bs[(nq + 0) * AS_K + k] = v.x;
            Bs[(nq + 1) * AS_K + k] = v.y;
            Bs[(nq + 2) * AS_K + k] = v.z;
            Bs[(nq + 3) * AS_K + k] = v.w;
        }
        __syncthreads();
#pragma unroll
        for (int kk = 0; kk < 8; kk++) {
            unsigned long long a2[8], b2[8];
#pragma unroll
            for (int i = 0; i < 8; i++)
                a2[i] = *(const unsigned long long*)&As[(ty * 8 + i) * AS_K + 2 * kk];
#pragma unroll
            for (int j = 0; j < 8; j++)
                b2[j] = *(const unsigned long long*)&Bs[(tx + 16 * j) * AS_K + 2 * kk];
#pragma unroll
            for (int i = 0; i < 8; i++)
#pragma unroll
                for (int j = 0; j < 8; j++) fma2(acc2[i][j], a2[i], b2[j]);
        }
    }
    float bj[8];
#pragma unroll
    for (int j = 0; j < 8; j++) bj[j] = bias[n0 + tx + 16 * j];
#pragma unroll
    for (int i = 0; i < 8; i++) {
        float* crow = C + (size_t)(m0 + ty * 8 + i) * DD + n0;
#pragma unroll
        for (int j = 0; j < 8; j++) {
            float2 v = *reinterpret_cast<float2*>(&acc2[i][j]);
            crow[tx + 16 * j] = v.x + v.y + bj[j];
        }
    }
}

// ---------------- kernel 3: fused attention core ----------------------------
__global__ __launch_bounds__(256, 1) void attn_kernel(const float* __restrict__ mask) {
    extern __shared__ float sm[];
    float* r_s    = sm;                          // MM*DD = 32768
    float* w_s    = r_s + MM * DD;               // AT_NB*DD
    float* sw_s   = w_s + AT_NB * DD;            // AT_NB*MM*HH (scores->wts)
    float* mask_s = sw_s + AT_NB * MM * HH;      // 64
    __shared__ float c_s[HH];

    const int b   = blockIdx.y;
    const int n0  = blockIdx.x * AT_NB;
    const int tid = threadIdx.x;
    const int wid = tid >> 5, lane = tid & 31;

    const float4* rg = (const float4*)(d_r + (size_t)b * MM * DD);
    float4* rs4 = (float4*)r_s;
#pragma unroll 4
    for (int i = tid; i < MM * DD / 4; i += 256) rs4[i] = rg[i];
    const float4* wg = (const float4*)(d_w + (size_t)(b * NN + n0) * DD);
    float4* ws4 = (float4*)w_s;
#pragma unroll
    for (int i = tid; i < AT_NB * DD / 4; i += 256) ws4[i] = wg[i];
    if (tid < MM) mask_s[tid] = mask[b * MM + tid];
    if (tid < HH) c_s[tid] = d_c[tid];

    float vr[HH][16];
#pragma unroll
    for (int h = 0; h < HH; h++)
#pragma unroll
        for (int i = 0; i < 16; i++)
            vr[h][i] = d_v[h * DD + lane + 32 * i];

    __syncthreads();

#pragma unroll 1
    for (int nn = 0; nn < AT_NB; nn++) {
        float wreg[16];
#pragma unroll
        for (int i = 0; i < 16; i++) wreg[i] = w_s[nn * DD + lane + 32 * i];
#pragma unroll 1
        for (int mi = 0; mi < 8; mi++) {
            int m = wid * 8 + mi;
            const float* rrow = r_s + m * DD;
            float a0 = 0.f, a1 = 0.f, a2 = 0.f, a3 = 0.f;
#pragma unroll
            for (int i = 0; i < 16; i++) {
                float hv = fmaxf(wreg[i] * rrow[lane + 32 * i], 0.f);
                a0 = fmaf(hv, vr[0][i], a0);
                a1 = fmaf(hv, vr[1][i], a1);
                a2 = fmaf(hv, vr[2][i], a2);
                a3 = fmaf(hv, vr[3][i], a3);
            }
#pragma unroll
            for (int off = 16; off; off >>= 1) {
                a0 += __shfl_xor_sync(0xffffffffu, a0, off);
                a1 += __shfl_xor_sync(0xffffffffu, a1, off);
                a2 += __shfl_xor_sync(0xffffffffu, a2, off);
                a3 += __shfl_xor_sync(0xffffffffu, a3, off);
            }
            if (lane == 0) {
                float* sp = sw_s + (nn * MM + m) * HH;
                sp[0] = a0 + c_s[0]; sp[1] = a1 + c_s[1];
                sp[2] = a2 + c_s[2]; sp[3] = a3 + c_s[3];
            }
        }
    }
    __syncthreads();

    for (int p = wid; p < AT_NB * HH; p += 8) {
        int nn = p >> 2, h = p & 3;
        float x0 = sw_s[(nn * MM + lane) * HH + h];
        float x1 = sw_s[(nn * MM + lane + 32) * HH + h];
        float mx = fmaxf(x0, x1);
#pragma unroll
        for (int off = 16; off; off >>= 1)
            mx = fmaxf(mx, __shfl_xor_sync(0xffffffffu, mx, off));
        float e0 = __expf(x0 - mx), e1 = __expf(x1 - mx);
        float s = e0 + e1;
#pragma unroll
        for (int off = 16; off; off >>= 1)
            s += __shfl_xor_sync(0xffffffffu, s, off);
        float inv = 1.f / s;
        float w0 = e0 * inv * mask_s[lane];
        float w1 = e1 * inv * mask_s[lane + 32];
        sw_s[(nn * MM + lane) * HH + h] = w0;
        sw_s[(nn * MM + lane + 32) * HH + h] = w1;
        float ws = w0 + w1;
#pragma unroll
        for (int off = 16; off; off >>= 1)
            ws += __shfl_xor_sync(0xffffffffu, ws, off);
        if (lane == 0) atomicAdd(&d_Wsum[b * HH + h], ws * (1.f / (float)NN));
    }
    __syncthreads();

    const int dA = tid, dB = tid + 256;
    float g[HH][2] = {};
#pragma unroll 1
    for (int nn = 0; nn < AT_NB; nn++) {
        float wn0 = w_s[nn * DD + dA], wn1 = w_s[nn * DD + dB];
        const float* swp = sw_s + nn * MM * HH;
#pragma unroll 4
        for (int m = 0; m < MM; m++) {
            float hv0 = fmaxf(wn0 * r_s[m * DD + dA], 0.f);
            float hv1 = fmaxf(wn1 * r_s[m * DD + dB], 0.f);
            float4 t = *(const float4*)(swp + m * HH);
            g[0][0] = fmaf(t.x, hv0, g[0][0]); g[0][1] = fmaf(t.x, hv1, g[0][1]);
            g[1][0] = fmaf(t.y, hv0, g[1][0]); g[1][1] = fmaf(t.y, hv1, g[1][1]);
            g[2][0] = fmaf(t.z, hv0, g[2][0]); g[2][1] = fmaf(t.z, hv1, g[2][1]);
            g[3][0] = fmaf(t.w, hv0, g[3][0]); g[3][1] = fmaf(t.w, hv1, g[3][1]);
        }
    }
#pragma unroll
    for (int h = 0; h < HH; h++) {
        atomicAdd(&d_G[(b * HH + h) * DD + dA], g[h][0] * (1.f / (float)NN));
        atomicAdd(&d_G[(b * HH + h) * DD + dB], g[h][1] * (1.f / (float)NN));
    }
}

// ---------------- kernel 4: head proj, weight-reuse over batch -------------
// grid (HH, 16 d-chunks of 32). Each thread: 1 k, 16 d's, 16 batch accs.
__global__ __launch_bounds__(256) void head_kernel(
    const float* __restrict__ lin_w, const float* __restrict__ lin_b) {
    const int h = blockIdx.x, dc = blockIdx.y;
    const int d0 = dc * 32;
    const int tid = threadIdx.x;
    const int k = tid & 127, half = tid >> 7;
    __shared__ float Gs[BB][32];
    __shared__ float Ws[BB];
    for (int i = tid; i < BB * 32; i += 256)
        Gs[i >> 5][i & 31] = d_G[((i >> 5) * HH + h) * DD + d0 + (i & 31)];
    if (tid < BB) Ws[tid] = d_Wsum[tid * HH + h];
    __syncthreads();

    float acc[BB];
    if (dc == 0 && half == 0) {
        float lb = lin_b[h * KK + k];
#pragma unroll
        for (int b = 0; b < BB; b++) acc[b] = Ws[b] * lb;
    } else {
#pragma unroll
        for (int b = 0; b < BB; b++) acc[b] = 0.f;
    }
#pragma unroll
    for (int dd = 0; dd < 16; dd++) {
        int d = d0 + half * 16 + dd;
        float lw = lin_w[((size_t)h * DD + d) * KK + k];
#pragma unroll
        for (int b = 0; b < BB; b++)
            acc[b] = fmaf(Gs[b][half * 16 + dd], lw, acc[b]);
    }
#pragma unroll
    for (int b = 0; b < BB; b++)
        atomicAdd(&d_head[b * DD + h * KK + k], acc[b]);
}

// ---------------- kernel 5: final proj, weight-reuse over batch ------------
// grid (4 j-tiles, 16 i-chunks of 32). d_o2 pre-seeded with final_b.
__global__ __launch_bounds__(256) void final_kernel(
    const float* __restrict__ final_w) {
    const int j0 = blockIdx.x * 128, i0 = blockIdx.y * 32;
    const int tid = threadIdx.x;
    const int j = j0 + (tid & 127), half = tid >> 7;
    __shared__ float hs[BB][32];
    for (int i = tid; i < BB * 32; i += 256)
        hs[i >> 5][i & 31] = d_head[(i >> 5) * DD + i0 + (i & 31)];
    __syncthreads();

    float acc[BB];
#pragma unroll
    for (int b = 0; b < BB; b++) acc[b] = 0.f;
#pragma unroll
    for (int ii = 0; ii < 16; ii++) {
        int i = i0 + half * 16 + ii;
        float fw = final_w[(size_t)i * DD + j];
#pragma unroll
        for (int b = 0; b < BB; b++)
            acc[b] = fmaf(hs[b][half * 16 + ii], fw, acc[b]);
    }
#pragma unroll
    for (int b = 0; b < BB; b++)
        atomicAdd(&d_o2[b * DD + j], acc[b]);
}

// ---------------- kernel 6: fc logits (relu applied on read) ---------------
__global__ __launch_bounds__(128) void fc_kernel(
    const float* __restrict__ fc_w, const float* __restrict__ fc_b,
    float* __restrict__ out) {
    const int b = blockIdx.x;
    const int tid = threadIdx.x;
    const int wid = tid >> 5, lane = tid & 31;
    __shared__ float os[DD];
    for (int i = tid; i < DD; i += 128)
        os[i] = fmaxf(d_o2[b * DD + i], 0.f);
    __syncthreads();
    if (wid < LL) {
        float acc = 0.f;
#pragma unroll 4
        for (int i = lane; i < DD; i += 32)
            acc = fmaf(os[i], fc_w[i * LL + wid], acc);
#pragma unroll
        for (int off = 16; off; off >>= 1)
            acc += __shfl_xor_sync(0xffffffffu, acc, off);
        if (lane == 0) out[b * LL + wid] = acc + fc_b[wid];
    }
}

// ---------------- launcher ---------------------------------------------------
extern "C" void kernel_launch(void* const* d_in, const int* in_sizes, int n_in,
                              void* d_out, int out_size) {
    const float* word    = (const float*)d_in[0];
    const float* rel     = (const float*)d_in[1];
    const float* mask    = (const float*)d_in[2];
    const float* Wn_w    = (const float*)d_in[3];
    const float* Wn_b    = (const float*)d_in[4];
    const float* Wr_w    = (const float*)d_in[5];
    const float* Wr_b    = (const float*)d_in[6];
    const float* lin_w   = (const float*)d_in[7];
    const float* lin_b   = (const float*)d_in[8];
    const float* score_w = (const float*)d_in[9];
    const float* score_b = (const float*)d_in[10];
    const float* final_w = (const float*)d_in[11];
    const float* final_b = (const float*)d_in[12];
    const float* fc_w    = (const float*)d_in[13];
    const float* fc_b    = (const float*)d_in[14];
    float* out = (float*)d_out;

    init_kernel<<<16, 256>>>(lin_w, lin_b, score_w, score_b, final_b);

    gemm_kernel<<<dim3(DD / 128, (BB * NN) / 128, 2), 256>>>(
        word, Wn_w, Wn_b, rel, Wr_w, Wr_b);

    const int smem_bytes = (MM * DD + AT_NB * DD + AT_NB * MM * HH + 64) * 4;
    cudaFuncSetAttribute(attn_kernel,
                         cudaFuncAttributeMaxDynamicSharedMemorySize, smem_bytes);
    attn_kernel<<<dim3(NN / AT_NB, BB), 256, smem_bytes>>>(mask);

    head_kernel<<<dim3(HH, 16), 256>>>(lin_w, lin_b);
    final_kernel<<<dim3(4, 16), 256>>>(final_w);
    fc_kernel<<<BB, 128>>>(fc_w, fc_b, out);
}

// round 4
// speedup vs baseline: 1.3263x; 1.0653x over previous
#include <cuda_runtime.h>
#include <math.h>

#define BB 16
#define NN 128
#define MM 64
#define DD 512
#define HH 4
#define KK 128
#define LL 3
#define AT_NB 8

// ---------------- scratch (device globals; no allocation allowed) ----------
__device__ float d_w[BB * NN * DD];      // word projection  [B,N,D]
__device__ float d_r[BB * MM * DD];      // rel projection   [B,M,D]
__device__ float d_v[HH * DD];           // lin_w . score_w  [H,D]
__device__ float d_c[HH];                // lin_b . score_w + score_b
__device__ float d_G[BB * HH * DD];      // mean_n sum_m wts*had  [B,H,D]
__device__ float d_Wsum[BB * HH];        // mean_n sum_m wts      [B,H]
__device__ float d_head[BB * DD];        // concat heads          [B,D]
__device__ float d_o2[BB * DD];          // final proj pre-relu   [B,D]

typedef unsigned long long u64;

// packed dual-fp32 fma (sm_100+; ptxas never emits from C++)
__device__ __forceinline__ void fma2(u64& d, u64 a, u64 b) {
    asm("fma.rn.f32x2 %0, %1, %2, %3;" : "=l"(d) : "l"(a), "l"(b), "l"(d));
}
__device__ __forceinline__ u64 pk(float x, float y) {
    u64 r;
    asm("mov.b64 %0, {%1, %2};" : "=l"(r) : "f"(x), "f"(y));
    return r;
}
__device__ __forceinline__ float2 upk(u64 v) {
    float2 r;
    asm("mov.b64 {%0, %1}, %2;" : "=f"(r.x), "=f"(r.y) : "l"(v));
    return r;
}

// ---------------- kernel 1: precompute v, c; init accumulators -------------
__global__ void init_kernel(const float* __restrict__ lin_w,
                            const float* __restrict__ lin_b,
                            const float* __restrict__ score_w,
                            const float* __restrict__ score_b,
                            const float* __restrict__ final_b) {
    int gid = blockIdx.x * blockDim.x + threadIdx.x;   // 4096 threads
    if (gid < HH * DD) {
        int h = gid >> 9, d = gid & (DD - 1);
        const float* lp = lin_w + (h * DD + d) * KK;
        const float* sp = score_w + h * KK;
        float acc = 0.f;
#pragma unroll 8
        for (int k = 0; k < KK; k++) acc = fmaf(lp[k], sp[k], acc);
        d_v[gid] = acc;
    } else if (gid < HH * DD + HH) {
        int h = gid - HH * DD;
        float acc = score_b[h];
        for (int k = 0; k < KK; k++)
            acc = fmaf(lin_b[h * KK + k], score_w[h * KK + k], acc);
        d_c[h] = acc;
    }
    for (int i = gid; i < BB * HH * DD; i += 4096) d_G[i] = 0.f;
    for (int i = gid; i < BB * DD; i += 4096) {
        d_head[i] = 0.f;
        d_o2[i] = final_b[i & (DD - 1)];
    }
    if (gid < BB * HH) d_Wsum[gid] = 0.f;
}

// ---------------- kernel 2: projections GEMM, 64x64 tiles, f32x2 -----------
#define AS_K 18   // padded k-stride (words), even for LDS.64 alignment
__global__ __launch_bounds__(256) void gemm_kernel(
    const float* __restrict__ word, const float* __restrict__ Wn_w,
    const float* __restrict__ Wn_b, const float* __restrict__ rel,
    const float* __restrict__ Wr_w, const float* __restrict__ Wr_b) {
    const int z = blockIdx.z;
    const int mtiles = (z == 0) ? (BB * NN / 64) : (BB * MM / 64);
    if ((int)blockIdx.y >= mtiles) return;
    const float* A    = (z == 0) ? word : rel;
    const float* W    = (z == 0) ? Wn_w : Wr_w;
    const float* bias = (z == 0) ? Wn_b : Wr_b;
    float* C          = (z == 0) ? d_w : d_r;

    __shared__ __align__(16) float As[64 * AS_K];  // [m][k] k-minor
    __shared__ __align__(16) float Bs[64 * AS_K];  // [n][k] k-minor

    const int tid = threadIdx.x;
    const int m0 = blockIdx.y * 64;
    const int n0 = blockIdx.x * 64;
    const int ty = tid >> 4, tx = tid & 15;

    // staging indices
    const int am = tid >> 2, akq = (tid & 3) * 4;     // A: 64m x 16k
    const int bk = tid >> 4, bnq = (tid & 15) * 4;    // B: 16k x 64n

    u64 acc2[4][4];
#pragma unroll
    for (int i = 0; i < 4; i++)
#pragma unroll
        for (int j = 0; j < 4; j++) acc2[i][j] = 0ull;

    for (int k0 = 0; k0 < DD; k0 += 16) {
        float4 av = *(const float4*)(A + (size_t)(m0 + am) * DD + k0 + akq);
        float4 bv = *(const float4*)(W + (size_t)(k0 + bk) * DD + n0 + bnq);
        __syncthreads();
        {
            float2* pa = (float2*)&As[am * AS_K + akq];
            pa[0] = make_float2(av.x, av.y);
            pa[1] = make_float2(av.z, av.w);
        }
        Bs[(bnq + 0) * AS_K + bk] = bv.x;
        Bs[(bnq + 1) * AS_K + bk] = bv.y;
        Bs[(bnq + 2) * AS_K + bk] = bv.z;
        Bs[(bnq + 3) * AS_K + bk] = bv.w;
        __syncthreads();
#pragma unroll
        for (int kk = 0; kk < 8; kk++) {
            u64 a2[4], b2[4];
#pragma unroll
            for (int i = 0; i < 4; i++)
                a2[i] = *(const u64*)&As[(ty + 16 * i) * AS_K + 2 * kk];
#pragma unroll
            for (int j = 0; j < 4; j++)
                b2[j] = *(const u64*)&Bs[(tx + 16 * j) * AS_K + 2 * kk];
#pragma unroll
            for (int i = 0; i < 4; i++)
#pragma unroll
                for (int j = 0; j < 4; j++) fma2(acc2[i][j], a2[i], b2[j]);
        }
    }
#pragma unroll
    for (int i = 0; i < 4; i++) {
        float* crow = C + (size_t)(m0 + ty + 16 * i) * DD + n0;
#pragma unroll
        for (int j = 0; j < 4; j++) {
            float2 v = upk(acc2[i][j]);
            crow[tx + 16 * j] = v.x + v.y + bias[n0 + tx + 16 * j];
        }
    }
}

// ---------------- kernel 3: fused attention core (f32x2) --------------------
// One CTA per (b, tile of AT_NB n's). r[b] in SMEM, v packed in registers.
__global__ __launch_bounds__(256, 1) void attn_kernel(const float* __restrict__ mask) {
    extern __shared__ float sm[];
    float* r_s    = sm;                          // MM*DD = 32768 fl
    float* w_s    = r_s + MM * DD;               // AT_NB*DD = 4096 fl
    float* sw_s   = w_s + AT_NB * DD;            // AT_NB*MM*HH*2 = 4096 fl (dup wts)
    float* mask_s = sw_s + AT_NB * MM * HH * 2;  // 64
    __shared__ float c_s[HH];

    const int b   = blockIdx.y;
    const int n0  = blockIdx.x * AT_NB;
    const int tid = threadIdx.x;
    const int wid = tid >> 5, lane = tid & 31;

    const float4* rg = (const float4*)(d_r + (size_t)b * MM * DD);
    float4* rs4 = (float4*)r_s;
#pragma unroll 4
    for (int i = tid; i < MM * DD / 4; i += 256) rs4[i] = rg[i];
    const float4* wg = (const float4*)(d_w + (size_t)(b * NN + n0) * DD);
    float4* ws4 = (float4*)w_s;
#pragma unroll
    for (int i = tid; i < AT_NB * DD / 4; i += 256) ws4[i] = wg[i];
    if (tid < MM) mask_s[tid] = mask[b * MM + tid];
    if (tid < HH) c_s[tid] = d_c[tid];

    // v packed: per-lane d-pairs d = 2*lane + 64*i
    u64 vr2[HH][8];
#pragma unroll
    for (int h = 0; h < HH; h++)
#pragma unroll
        for (int i = 0; i < 8; i++) {
            float2 vv = *(const float2*)&d_v[h * DD + 2 * lane + 64 * i];
            vr2[h][i] = pk(vv.x, vv.y);
        }

    __syncthreads();

    // ---- pass 1: scores -> sw_s[(nn*MM+m)*8 + 2h] ----
#pragma unroll 1
    for (int nn = 0; nn < AT_NB; nn++) {
        float2 w2[8];
#pragma unroll
        for (int i = 0; i < 8; i++)
            w2[i] = *(const float2*)&w_s[nn * DD + 2 * lane + 64 * i];
#pragma unroll 1
        for (int mi = 0; mi < 8; mi++) {
            int m = wid * 8 + mi;
            const float* rrow = r_s + m * DD + 2 * lane;
            u64 a0 = 0, a1 = 0, a2 = 0, a3 = 0;
#pragma unroll
            for (int i = 0; i < 8; i++) {
                float2 rv = *(const float2*)&rrow[64 * i];
                float hx = fmaxf(w2[i].x * rv.x, 0.f);
                float hy = fmaxf(w2[i].y * rv.y, 0.f);
                u64 hv = pk(hx, hy);
                fma2(a0, hv, vr2[0][i]);
                fma2(a1, hv, vr2[1][i]);
                fma2(a2, hv, vr2[2][i]);
                fma2(a3, hv, vr2[3][i]);
            }
            float2 A0 = upk(a0), A1 = upk(a1), A2 = upk(a2), A3 = upk(a3);
            float s0 = A0.x + A0.y, s1 = A1.x + A1.y;
            float s2 = A2.x + A2.y, s3 = A3.x + A3.y;
#pragma unroll
            for (int off = 16; off; off >>= 1) {
                s0 += __shfl_xor_sync(0xffffffffu, s0, off);
                s1 += __shfl_xor_sync(0xffffffffu, s1, off);
                s2 += __shfl_xor_sync(0xffffffffu, s2, off);
                s3 += __shfl_xor_sync(0xffffffffu, s3, off);
            }
            if (lane == 0) {
                float* sp = sw_s + (nn * MM + m) * 8;
                sp[0] = s0 + c_s[0]; sp[2] = s1 + c_s[1];
                sp[4] = s2 + c_s[2]; sp[6] = s3 + c_s[3];
            }
        }
    }
    __syncthreads();

    // ---- softmax over m; store DUPLICATED weights (t,t) pairs ----
    for (int p = wid; p < AT_NB * HH; p += 8) {
        int nn = p >> 2, h = p & 3;
        float x0 = sw_s[(nn * MM + lane) * 8 + 2 * h];
        float x1 = sw_s[(nn * MM + lane + 32) * 8 + 2 * h];
        float mx = fmaxf(x0, x1);
#pragma unroll
        for (int off = 16; off; off >>= 1)
            mx = fmaxf(mx, __shfl_xor_sync(0xffffffffu, mx, off));
        float e0 = __expf(x0 - mx), e1 = __expf(x1 - mx);
        float s = e0 + e1;
#pragma unroll
        for (int off = 16; off; off >>= 1)
            s += __shfl_xor_sync(0xffffffffu, s, off);
        float inv = 1.f / s;
        float w0 = e0 * inv * mask_s[lane];
        float w1 = e1 * inv * mask_s[lane + 32];
        float* p0 = sw_s + (nn * MM + lane) * 8 + 2 * h;
        float* p1 = sw_s + (nn * MM + lane + 32) * 8 + 2 * h;
        p0[0] = w0; p0[1] = w0;
        p1[0] = w1; p1[1] = w1;
        float ws = w0 + w1;
#pragma unroll
        for (int off = 16; off; off >>= 1)
            ws += __shfl_xor_sync(0xffffffffu, ws, off);
        if (lane == 0) atomicAdd(&d_Wsum[b * HH + h], ws * (1.f / (float)NN));
    }
    __syncthreads();

    // ---- pass 2: g[h][d-pair] via packed fma, 1 d-pair per thread ----
    const int dp = 2 * tid;                      // d pair (2*tid, 2*tid+1)
    u64 g2[HH] = {0ull, 0ull, 0ull, 0ull};
#pragma unroll 1
    for (int nn = 0; nn < AT_NB; nn++) {
        float2 wv = *(const float2*)&w_s[nn * DD + dp];
        const float* swp = sw_s + nn * MM * 8;
#pragma unroll 4
        for (int m = 0; m < MM; m++) {
            float2 rv = *(const float2*)&r_s[m * DD + dp];
            float hx = fmaxf(wv.x * rv.x, 0.f);
            float hy = fmaxf(wv.y * rv.y, 0.f);
            u64 hv = pk(hx, hy);
            longlong2 q0 = *(const longlong2*)(swp + m * 8);      // (t0,t0),(t1,t1)
            longlong2 q1 = *(const longlong2*)(swp + m * 8 + 4);  // (t2,t2),(t3,t3)
            fma2(g2[0], hv, (u64)q0.x);
            fma2(g2[1], hv, (u64)q0.y);
            fma2(g2[2], hv, (u64)q1.x);
            fma2(g2[3], hv, (u64)q1.y);
        }
    }
#pragma unroll
    for (int h = 0; h < HH; h++) {
        float2 gv = upk(g2[h]);
        atomicAdd(&d_G[(b * HH + h) * DD + dp + 0], gv.x * (1.f / (float)NN));
        atomicAdd(&d_G[(b * HH + h) * DD + dp + 1], gv.y * (1.f / (float)NN));
    }
}

// ---------------- kernel 4: head proj, weight-reuse over batch -------------
__global__ __launch_bounds__(256) void head_kernel(
    const float* __restrict__ lin_w, const float* __restrict__ lin_b) {
    const int h = blockIdx.x, dc = blockIdx.y;
    const int d0 = dc * 32;
    const int tid = threadIdx.x;
    const int k = tid & 127, half = tid >> 7;
    __shared__ float Gs[BB][32];
    __shared__ float Ws[BB];
    for (int i = tid; i < BB * 32; i += 256)
        Gs[i >> 5][i & 31] = d_G[((i >> 5) * HH + h) * DD + d0 + (i & 31)];
    if (tid < BB) Ws[tid] = d_Wsum[tid * HH + h];
    __syncthreads();

    float acc[BB];
    if (dc == 0 && half == 0) {
        float lb = lin_b[h * KK + k];
#pragma unroll
        for (int b = 0; b < BB; b++) acc[b] = Ws[b] * lb;
    } else {
#pragma unroll
        for (int b = 0; b < BB; b++) acc[b] = 0.f;
    }
#pragma unroll
    for (int dd = 0; dd < 16; dd++) {
        int d = d0 + half * 16 + dd;
        float lw = lin_w[((size_t)h * DD + d) * KK + k];
#pragma unroll
        for (int b = 0; b < BB; b++)
            acc[b] = fmaf(Gs[b][half * 16 + dd], lw, acc[b]);
    }
#pragma unroll
    for (int b = 0; b < BB; b++)
        atomicAdd(&d_head[b * DD + h * KK + k], acc[b]);
}

// ---------------- kernel 5: final proj, weight-reuse over batch ------------
__global__ __launch_bounds__(256) void final_kernel(
    const float* __restrict__ final_w) {
    const int j0 = blockIdx.x * 128, i0 = blockIdx.y * 32;
    const int tid = threadIdx.x;
    const int j = j0 + (tid & 127), half = tid >> 7;
    __shared__ float hs[BB][32];
    for (int i = tid; i < BB * 32; i += 256)
        hs[i >> 5][i & 31] = d_head[(i >> 5) * DD + i0 + (i & 31)];
    __syncthreads();

    float acc[BB];
#pragma unroll
    for (int b = 0; b < BB; b++) acc[b] = 0.f;
#pragma unroll
    for (int ii = 0; ii < 16; ii++) {
        int i = i0 + half * 16 + ii;
        float fw = final_w[(size_t)i * DD + j];
#pragma unroll
        for (int b = 0; b < BB; b++)
            acc[b] = fmaf(hs[b][half * 16 + ii], fw, acc[b]);
    }
#pragma unroll
    for (int b = 0; b < BB; b++)
        atomicAdd(&d_o2[b * DD + j], acc[b]);
}

// ---------------- kernel 6: fc logits (relu applied on read) ---------------
__global__ __launch_bounds__(128) void fc_kernel(
    const float* __restrict__ fc_w, const float* __restrict__ fc_b,
    float* __restrict__ out) {
    const int b = blockIdx.x;
    const int tid = threadIdx.x;
    const int wid = tid >> 5, lane = tid & 31;
    __shared__ float os[DD];
    for (int i = tid; i < DD; i += 128)
        os[i] = fmaxf(d_o2[b * DD + i], 0.f);
    __syncthreads();
    if (wid < LL) {
        float acc = 0.f;
#pragma unroll 4
        for (int i = lane; i < DD; i += 32)
            acc = fmaf(os[i], fc_w[i * LL + wid], acc);
#pragma unroll
        for (int off = 16; off; off >>= 1)
            acc += __shfl_xor_sync(0xffffffffu, acc, off);
        if (lane == 0) out[b * LL + wid] = acc + fc_b[wid];
    }
}

// ---------------- launcher ---------------------------------------------------
extern "C" void kernel_launch(void* const* d_in, const int* in_sizes, int n_in,
                              void* d_out, int out_size) {
    const float* word    = (const float*)d_in[0];
    const float* rel     = (const float*)d_in[1];
    const float* mask    = (const float*)d_in[2];
    const float* Wn_w    = (const float*)d_in[3];
    const float* Wn_b    = (const float*)d_in[4];
    const float* Wr_w    = (const float*)d_in[5];
    const float* Wr_b    = (const float*)d_in[6];
    const float* lin_w   = (const float*)d_in[7];
    const float* lin_b   = (const float*)d_in[8];
    const float* score_w = (const float*)d_in[9];
    const float* score_b = (const float*)d_in[10];
    const float* final_w = (const float*)d_in[11];
    const float* final_b = (const float*)d_in[12];
    const float* fc_w    = (const float*)d_in[13];
    const float* fc_b    = (const float*)d_in[14];
    float* out = (float*)d_out;

    init_kernel<<<16, 256>>>(lin_w, lin_b, score_w, score_b, final_b);

    gemm_kernel<<<dim3(DD / 64, (BB * NN) / 64, 2), 256>>>(
        word, Wn_w, Wn_b, rel, Wr_w, Wr_b);

    const int smem_bytes =
        (MM * DD + AT_NB * DD + AT_NB * MM * HH * 2 + 64) * 4;
    cudaFuncSetAttribute(attn_kernel,
                         cudaFuncAttributeMaxDynamicSharedMemorySize, smem_bytes);
    attn_kernel<<<dim3(NN / AT_NB, BB), 256, smem_bytes>>>(mask);

    head_kernel<<<dim3(HH, 16), 256>>>(lin_w, lin_b);
    final_kernel<<<dim3(4, 16), 256>>>(final_w);
    fc_kernel<<<BB, 128>>>(fc_w, fc_b, out);
}